// round 10
// baseline (speedup 1.0000x reference)
#include <cuda_runtime.h>
#include <math.h>

#define C    2048
#define GRID 148
#define NT   512
// dynamic smem (floats): s_a(2048) + s_b(2048) + s_hh(14*2048)
#define SMEM_BYTES ((2 * C + 14 * C) * 4)

typedef unsigned long long ull;

// ---------------- persistent-kernel scratch (device globals; no allocs) ----------------
__device__ __align__(16) float g_inp[C];
__device__ __align__(16) float g_hid[2][4][C];
__device__ __align__(16) float g_hraw[3][C];
__device__ __align__(16) float g_lp[2][C];
__device__ unsigned g_bar;

// Near-exact compensated accumulation: TwoProd (FMA) + Kahan, all RN intrinsics.
__device__ __forceinline__ void kacc(float a, float b, float& s, float& cmp, float& es) {
    float p = __fmul_rn(a, b);
    float e = __fmaf_rn(a, b, -p);
    float y = __fsub_rn(p, cmp);
    float t = __fadd_rn(s, y);
    cmp = __fsub_rn(__fsub_rn(t, s), y);
    s = t;
    es = __fadd_rn(es, e);
}
__device__ __forceinline__ void kacc4(float4 a, float4 b, float& s, float& c, float& e) {
    kacc(a.x, b.x, s, c, e); kacc(a.y, b.y, s, c, e);
    kacc(a.z, b.z, s, c, e); kacc(a.w, b.w, s, c, e);
}

// 256-bit (8-float) weight chunk; sm_103a needs v4.b64 width for L2 evict hints.
struct F8 { float4 lo, hi; };

__device__ __forceinline__ F8 unpack8(ull a, ull b, ull c, ull d) {
    F8 r;
    r.lo.x = __uint_as_float((unsigned)a); r.lo.y = __uint_as_float((unsigned)(a >> 32));
    r.lo.z = __uint_as_float((unsigned)b); r.lo.w = __uint_as_float((unsigned)(b >> 32));
    r.hi.x = __uint_as_float((unsigned)c); r.hi.y = __uint_as_float((unsigned)(c >> 32));
    r.hi.z = __uint_as_float((unsigned)d); r.hi.w = __uint_as_float((unsigned)(d >> 32));
    return r;
}

__device__ __forceinline__ F8 ldw8(const F8* p) {      // ih loads: evict_last
    ull a, b, c, d;
    asm("ld.global.nc.L2::evict_last.v4.b64 {%0,%1,%2,%3}, [%4];"
        : "=l"(a), "=l"(b), "=l"(c), "=l"(d) : "l"(p));
    return unpack8(a, b, c, d);
}
__device__ __forceinline__ F8 ldw8v(const F8* p) {     // volatile (pre-barrier prefetch)
    ull a, b, c, d;
    asm volatile("ld.global.nc.L2::evict_last.v4.b64 {%0,%1,%2,%3}, [%4];"
        : "=l"(a), "=l"(b), "=l"(c), "=l"(d) : "l"(p));
    return unpack8(a, b, c, d);
}

// cp.async stage of one 8KB weight row into shared (16 x 16B per lane, deep MLP).
__device__ __forceinline__ void stage_hh(unsigned smem_row, const float* grow,
                                         int lane, ull pol) {
#pragma unroll
    for (int i = 0; i < 16; i++) {
        unsigned d = smem_row + (unsigned)(lane + 32 * i) * 16u;
        const char* s = reinterpret_cast<const char*>(grow) + (size_t)(lane + 32 * i) * 16;
        asm volatile("cp.async.cg.shared.global.L2::cache_hint [%0], [%1], 16, %2;"
                     :: "r"(d), "l"(s), "l"(pol));
    }
    asm volatile("cp.async.commit_group;" ::: "memory");
}
__device__ __forceinline__ void wait_hh() {
    asm volatile("cp.async.wait_group 0;" ::: "memory");
    __syncwarp();
}

// Split grid barrier. All 148 CTAs co-resident.
__device__ __forceinline__ void gbar_arrive() {
    __syncthreads();
    if (threadIdx.x == 0) {
        __threadfence();
        atomicAdd(&g_bar, 1u);
    }
}
__device__ __forceinline__ void gbar_wait(unsigned target) {
    if (threadIdx.x == 0) {
        unsigned v;
        do {
            asm volatile("ld.global.acquire.gpu.u32 %0, [%1];"
                         : "=r"(v) : "l"(&g_bar) : "memory");
        } while (v < target);
    }
    __syncthreads();
}

__global__ void rnn_init(const float* __restrict__ x) {
    int i = blockIdx.x * blockDim.x + threadIdx.x;
    if (i == 0) g_bar = 0u;
    if (i < C) {
        g_inp[i] = 0.f;
        g_hid[0][0][i] = x[i];
        g_hid[0][1][i] = 0.f;
        g_hid[0][2][i] = 0.f;
        g_hid[0][3][i] = 0.f;
    }
}

// LengthProducer dot (one-shot traffic): scalar Kahan + fp64 reduce.
__device__ __forceinline__ float dotLP(const float* __restrict__ wrow,
                                       const float* __restrict__ v, int lane) {
    float s = 0.f, c = 0.f, e = 0.f;
    const float4* w4 = reinterpret_cast<const float4*>(wrow);
    const float4* v4 = reinterpret_cast<const float4*>(v);
#pragma unroll
    for (int i = 0; i < 16; i++) {
        float4 a = __ldg(w4 + lane + 32 * i);
        float4 b = v4[lane + 32 * i];
        kacc4(a, b, s, c, e);
    }
    double d = (double)s + (double)c + (double)e;
#pragma unroll
    for (int o = 16; o > 0; o >>= 1)
        d += __shfl_down_sync(0xffffffffu, d, o);
    return (float)d;
}

// One RNN phase. NPOL selects next phase's hh cp.async policy (0=evict_last, 1=evict_first).
template<int NPOL>
__device__ __forceinline__ void rnn_phase(
    int l, int t, int p, int nl, int np,
    int j, int w, int lane, int tid, unsigned& ph,
    const float* __restrict__ w_ih, const float* __restrict__ w_hh,
    const float* __restrict__ b_ih, const float* __restrict__ b_hh,
    float* __restrict__ out,
    float* s_a, float* s_b, const float* s_hh, unsigned hh_smem_row,
    ull polL, ull polF,
    F8& A0, F8& A1)
{
    gbar_wait(ph * GRID);                      // inputs published; s_b/hh staged pre-wait
    const float* vin = (l == 0) ? g_inp : g_hraw[l - 1];
    reinterpret_cast<float4*>(s_a)[tid] = reinterpret_cast<const float4*>(vin)[tid];
    __syncthreads();

    if (j < C) {
        const F8* wa8 = reinterpret_cast<const F8*>(w_ih + ((size_t)l * C + j) * C);
        const float4* a4 = reinterpret_cast<const float4*>(s_a);
        const float4* b4 = reinterpret_cast<const float4*>(s_b);
        const float4* hw4 = reinterpret_cast<const float4*>(s_hh + w * C);

        // fully preload ih row: 8 LDG.256 outstanding (A0,A1 prefetched across barrier)
        F8 W0 = A0, W1 = A1;
        F8 W2 = ldw8(wa8 + lane + 64);
        F8 W3 = ldw8(wa8 + lane + 96);
        F8 W4 = ldw8(wa8 + lane + 128);
        F8 W5 = ldw8(wa8 + lane + 160);
        F8 W6 = ldw8(wa8 + lane + 192);
        F8 W7 = ldw8(wa8 + lane + 224);

        wait_hh();                              // hh row staged last phase -> smem ready

        float sa = 0.f, ca = 0.f, ea = 0.f, sb = 0.f, cb = 0.f, eb = 0.f;
#pragma unroll
        for (int m = 0; m < 8; m++) {
            F8 Wm = (m == 0) ? W0 : (m == 1) ? W1 : (m == 2) ? W2 : (m == 3) ? W3
                  : (m == 4) ? W4 : (m == 5) ? W5 : (m == 6) ? W6 : W7;
            int tdx = lane + 32 * m;
            kacc4(Wm.lo, a4[2 * tdx],     sa, ca, ea);
            kacc4(Wm.hi, a4[2 * tdx + 1], sa, ca, ea);
            float4 h0 = hw4[2 * tdx], h1 = hw4[2 * tdx + 1];
            kacc4(h0, b4[2 * tdx],     sb, cb, eb);
            kacc4(h1, b4[2 * tdx + 1], sb, cb, eb);
        }
        double da = (double)sa + ca + ea;
        double db = (double)sb + cb + eb;
#pragma unroll
        for (int o = 16; o > 0; o >>= 1) {
            da += __shfl_down_sync(0xffffffffu, da, o);
            db += __shfl_down_sync(0xffffffffu, db, o);
        }
        if (lane == 0) {
            // ref rounding: ((dih + b_ih) + dhh) + b_hh, all fp32 RN
            float pre = __fadd_rn(__fadd_rn(__fadd_rn((float)da, b_ih[l * C + j]),
                                            (float)db), b_hh[l * C + j]);
            float h  = fmaxf(pre, 0.f);
            float n  = __fsqrt_rn(__fmul_rn(h, h));
            float hn = __fdiv_rn(h, __fadd_rn(n, 1e-12f));
            g_hid[p ^ 1][l][j] = hn;
            if (l < 3) g_hraw[l][j] = h;
            else { g_inp[j] = hn; out[(size_t)t * C + j] = hn; }
        }
    }

    // ---- tail: prefetch next ih chunk0 + cp.async next hh row (overlaps barrier) ----
    if (j < C) {
        const F8* na = reinterpret_cast<const F8*>(w_ih + ((size_t)nl * C + j) * C);
        A0 = ldw8v(na + lane); A1 = ldw8v(na + lane + 32);
        stage_hh(hh_smem_row, w_hh + ((size_t)nl * C + j) * C, lane,
                 (NPOL == 0) ? polL : polF);
    }
    gbar_arrive();
    // next phase's hid operand has been stable for >=3 barriers: stage pre-wait
    reinterpret_cast<float4*>(s_b)[tid] =
        reinterpret_cast<const float4*>(g_hid[np][nl])[tid];
    ++ph;
}

__global__ void __launch_bounds__(NT, 1) rnn_main(
    const float* __restrict__ x,
    const float* __restrict__ lp_w,  const float* __restrict__ lp_b,
    const float* __restrict__ lp_wout, const float* __restrict__ lp_bout,
    const float* __restrict__ w_ih,  const float* __restrict__ b_ih,
    const float* __restrict__ w_hh,  const float* __restrict__ b_hh,
    float* __restrict__ out, int T, int has_l)
{
    extern __shared__ float dsm[];
    float* s_a  = dsm;                 // 2048
    float* s_b  = dsm + C;             // 2048
    float* s_hh = dsm + 2 * C;         // 14 rows x 2048: warp w's hh row

    const int tid  = threadIdx.x;
    const int w    = tid >> 5;
    const int lane = tid & 31;
    const int bid  = blockIdx.x;
    const int j    = w * GRID + bid;
    unsigned ph = 0;

    ull polL, polF;
    asm("createpolicy.fractional.L2::evict_last.b64 %0, 1.0;"  : "=l"(polL));
    asm("createpolicy.fractional.L2::evict_first.b64 %0, 1.0;" : "=l"(polF));

    unsigned smem_base;
    {
        unsigned long long gp = __cvta_generic_to_shared(dsm);
        smem_base = (unsigned)gp;
    }
    const unsigned hh_smem_row = smem_base + (unsigned)(2 * C + w * C) * 4u;

    // ---------------- LengthProducer: 3 hidden Linear + LeakyReLU(0.2) ----------------
    for (int i = 0; i < 3; i++) {
        const float* vin = (i == 0) ? x : g_lp[(i - 1) & 1];
        reinterpret_cast<float4*>(s_a)[tid] = reinterpret_cast<const float4*>(vin)[tid];
        __syncthreads();
        if (j < C) {
            float d = dotLP(lp_w + (size_t)i * C * C + (size_t)j * C, s_a, lane);
            if (lane == 0) {
                float z = __fadd_rn(d, lp_b[i * C + j]);
                g_lp[i & 1][j] = (z >= 0.f) ? z : __fmul_rn(0.2f, z);
            }
        }
        gbar_arrive(); ++ph; gbar_wait(ph * GRID);
    }
    // ---------------- LP output scalar: l = min(|y@wout + bout|, 0.9999) ----------------
    if (bid == 0 && w == 0) {
        float d = dotLP(lp_wout, g_lp[0], lane);
        if (lane == 0 && has_l > 0) {
            float z = __fadd_rn(d, lp_bout[0]);
            out[(size_t)T * C] = fminf(fabsf(z), 0.9999f);
        }
    }
    // prologue for RNN (t=0,l=0): prefetch ih chunk0 + stage hh row + stage s_b
    F8 A0, A1;
    if (j < C) {
        const F8* na = reinterpret_cast<const F8*>(w_ih + (size_t)j * C);
        A0 = ldw8v(na + lane); A1 = ldw8v(na + lane + 32);
        stage_hh(hh_smem_row, w_hh + (size_t)j * C, lane, polL);
    }
    gbar_arrive();
    reinterpret_cast<float4*>(s_b)[tid] = reinterpret_cast<const float4*>(g_hid[0][0])[tid];
    ++ph;

    // ---------------- 4-layer ReLU RNN scan, T steps ----------------
    // hh rows staged one phase ahead via cp.async (deep MLP); ih rows fully preloaded
    // in registers. hh layers 0-1 evict_last, 2-3 evict_first; ih evict_last.
    for (int t = 0; t < T; t++) {
        const int p = t & 1;
        rnn_phase<0>(0, t, p, 1, p,     j, w, lane, tid, ph, w_ih, w_hh, b_ih, b_hh,
                     out, s_a, s_b, s_hh, hh_smem_row, polL, polF, A0, A1);
        rnn_phase<1>(1, t, p, 2, p,     j, w, lane, tid, ph, w_ih, w_hh, b_ih, b_hh,
                     out, s_a, s_b, s_hh, hh_smem_row, polL, polF, A0, A1);
        rnn_phase<1>(2, t, p, 3, p,     j, w, lane, tid, ph, w_ih, w_hh, b_ih, b_hh,
                     out, s_a, s_b, s_hh, hh_smem_row, polL, polF, A0, A1);
        rnn_phase<0>(3, t, p, 0, p ^ 1, j, w, lane, tid, ph, w_ih, w_hh, b_ih, b_hh,
                     out, s_a, s_b, s_hh, hh_smem_row, polL, polF, A0, A1);
    }
}

extern "C" void kernel_launch(void* const* d_in, const int* in_sizes, int n_in,
                              void* d_out, int out_size) {
    const float* x       = (const float*)d_in[0];
    const float* lp_w    = (const float*)d_in[1];
    const float* lp_b    = (const float*)d_in[2];
    const float* lp_wout = (const float*)d_in[3];
    const float* lp_bout = (const float*)d_in[4];
    const float* w_ih    = (const float*)d_in[5];
    const float* b_ih    = (const float*)d_in[6];
    const float* w_hh    = (const float*)d_in[7];
    const float* b_hh    = (const float*)d_in[8];
    float* out = (float*)d_out;

    int T     = out_size / C;        // 512 seq rows
    int has_l = out_size - T * C;    // trailing scalar l present?

    cudaFuncSetAttribute(rnn_main, cudaFuncAttributeMaxDynamicSharedMemorySize, SMEM_BYTES);

    rnn_init<<<8, 256>>>(x);
    rnn_main<<<GRID, NT, SMEM_BYTES>>>(x, lp_w, lp_b, lp_wout, lp_bout,
                                       w_ih, b_ih, w_hh, b_hh, out, T, has_l);
}

// round 11
// speedup vs baseline: 1.1323x; 1.1323x over previous
#include <cuda_runtime.h>
#include <math.h>

#define C    2048
#define GRID 148
#define NT   512
// dynamic smem (floats): s_a(2048) + s_n(2048) + 14 hh rows (14*2048)
#define SMEM_BYTES ((2 * C + 14 * C) * 4)

typedef unsigned long long ull;

// ---------------- persistent-kernel scratch (device globals; no allocs) ----------------
__device__ __align__(16) float g_inp[C];          // normalized h3 (RNN input vector)
__device__ __align__(16) float g_hidn[3][C];      // normalized h0..h2 of current step
__device__ __align__(16) float g_hraw[3][C];      // raw relu h0..h2 of current step
__device__ __align__(16) float g_lp[2][C];
__device__ unsigned g_bar;

// Near-exact compensated accumulation: TwoProd (FMA) + Kahan, all RN intrinsics.
__device__ __forceinline__ void kacc(float a, float b, float& s, float& cmp, float& es) {
    float p = __fmul_rn(a, b);
    float e = __fmaf_rn(a, b, -p);
    float y = __fsub_rn(p, cmp);
    float t = __fadd_rn(s, y);
    cmp = __fsub_rn(__fsub_rn(t, s), y);
    s = t;
    es = __fadd_rn(es, e);
}
__device__ __forceinline__ void kacc4(float4 a, float4 b, float& s, float& c, float& e) {
    kacc(a.x, b.x, s, c, e); kacc(a.y, b.y, s, c, e);
    kacc(a.z, b.z, s, c, e); kacc(a.w, b.w, s, c, e);
}

// 256-bit (8-float) weight chunk; sm_103a needs v4.b64 width for L2 evict hints.
struct F8 { float4 lo, hi; };

__device__ __forceinline__ F8 unpack8(ull a, ull b, ull c, ull d) {
    F8 r;
    r.lo.x = __uint_as_float((unsigned)a); r.lo.y = __uint_as_float((unsigned)(a >> 32));
    r.lo.z = __uint_as_float((unsigned)b); r.lo.w = __uint_as_float((unsigned)(b >> 32));
    r.hi.x = __uint_as_float((unsigned)c); r.hi.y = __uint_as_float((unsigned)(c >> 32));
    r.hi.z = __uint_as_float((unsigned)d); r.hi.w = __uint_as_float((unsigned)(d >> 32));
    return r;
}
__device__ __forceinline__ F8 ldw8(const F8* p) {       // evict_last
    ull a, b, c, d;
    asm("ld.global.nc.L2::evict_last.v4.b64 {%0,%1,%2,%3}, [%4];"
        : "=l"(a), "=l"(b), "=l"(c), "=l"(d) : "l"(p));
    return unpack8(a, b, c, d);
}
__device__ __forceinline__ F8 ldw8v(const F8* p) {      // volatile (cross-barrier prefetch)
    ull a, b, c, d;
    asm volatile("ld.global.nc.L2::evict_last.v4.b64 {%0,%1,%2,%3}, [%4];"
        : "=l"(a), "=l"(b), "=l"(c), "=l"(d) : "l"(p));
    return unpack8(a, b, c, d);
}

// Full weight row (64 floats/lane = 8 slots) preloaded in registers.
struct Row8 { F8 r0, r1, r2, r3, r4, r5, r6, r7; };

__device__ __forceinline__ void preload_row(Row8& R, const F8* b, int lane) {
    R.r0 = ldw8v(b + lane);       R.r1 = ldw8v(b + lane + 32);
    R.r2 = ldw8v(b + lane + 64);  R.r3 = ldw8v(b + lane + 96);
    R.r4 = ldw8v(b + lane + 128); R.r5 = ldw8v(b + lane + 160);
    R.r6 = ldw8v(b + lane + 192); R.r7 = ldw8v(b + lane + 224);
}
// Dot of a preloaded row with smem activations. Slot order: lane, lane+32, ..., lane+224
// (identical to rounds 3-10 -> bit-identical exact dot).
__device__ __forceinline__ double row_dot(const Row8& R, const float4* a4, int lane) {
    float s = 0.f, c = 0.f, e = 0.f;
    int t;
    t = lane;       kacc4(R.r0.lo, a4[2*t], s,c,e); kacc4(R.r0.hi, a4[2*t+1], s,c,e);
    t = lane + 32;  kacc4(R.r1.lo, a4[2*t], s,c,e); kacc4(R.r1.hi, a4[2*t+1], s,c,e);
    t = lane + 64;  kacc4(R.r2.lo, a4[2*t], s,c,e); kacc4(R.r2.hi, a4[2*t+1], s,c,e);
    t = lane + 96;  kacc4(R.r3.lo, a4[2*t], s,c,e); kacc4(R.r3.hi, a4[2*t+1], s,c,e);
    t = lane + 128; kacc4(R.r4.lo, a4[2*t], s,c,e); kacc4(R.r4.hi, a4[2*t+1], s,c,e);
    t = lane + 160; kacc4(R.r5.lo, a4[2*t], s,c,e); kacc4(R.r5.hi, a4[2*t+1], s,c,e);
    t = lane + 192; kacc4(R.r6.lo, a4[2*t], s,c,e); kacc4(R.r6.hi, a4[2*t+1], s,c,e);
    t = lane + 224; kacc4(R.r7.lo, a4[2*t], s,c,e); kacc4(R.r7.hi, a4[2*t+1], s,c,e);
    return (double)s + c + e;
}
// Dot of an smem-staged weight row with smem activations (shadow hh dot).
__device__ __forceinline__ double smem_dot(const float4* __restrict__ w4,
                                           const float4* __restrict__ n4, int lane) {
    float s = 0.f, c = 0.f, e = 0.f;
#pragma unroll
    for (int m = 0; m < 8; m++) {
        int t = lane + 32 * m;
        kacc4(w4[2*t],   n4[2*t],   s, c, e);
        kacc4(w4[2*t+1], n4[2*t+1], s, c, e);
    }
    return (double)s + c + e;
}

// cp.async stage of one 8KB hh weight row into my smem row.
__device__ __forceinline__ void stage_hh(unsigned smem_row, const float* grow,
                                         int lane, ull pol) {
#pragma unroll
    for (int i = 0; i < 16; i++) {
        unsigned d = smem_row + (unsigned)(lane + 32 * i) * 16u;
        const char* s = reinterpret_cast<const char*>(grow) + (size_t)(lane + 32 * i) * 16;
        asm volatile("cp.async.cg.shared.global.L2::cache_hint [%0], [%1], 16, %2;"
                     :: "r"(d), "l"(s), "l"(pol));
    }
    asm volatile("cp.async.commit_group;" ::: "memory");
}

// Split grid barrier. All 148 CTAs co-resident.
__device__ __forceinline__ void gbar_arrive() {
    __syncthreads();
    if (threadIdx.x == 0) {
        __threadfence();
        atomicAdd(&g_bar, 1u);
    }
}
__device__ __forceinline__ void gbar_wait(unsigned target) {
    if (threadIdx.x == 0) {
        unsigned v;
        do {
            asm volatile("ld.global.acquire.gpu.u32 %0, [%1];"
                         : "=r"(v) : "l"(&g_bar) : "memory");
        } while (v < target);
    }
    __syncthreads();
}

__global__ void rnn_init(const float* __restrict__ x) {
    int i = blockIdx.x * blockDim.x + threadIdx.x;
    if (i == 0) g_bar = 0u;
    if (i < C) g_inp[i] = 0.f;
}

// LengthProducer dot (one-shot traffic): scalar Kahan + fp64 reduce.
__device__ __forceinline__ float dotLP(const float* __restrict__ wrow,
                                       const float* __restrict__ v, int lane) {
    float s = 0.f, c = 0.f, e = 0.f;
    const float4* w4 = reinterpret_cast<const float4*>(wrow);
    const float4* v4 = reinterpret_cast<const float4*>(v);
#pragma unroll
    for (int i = 0; i < 16; i++) {
        float4 a = __ldg(w4 + lane + 32 * i);
        float4 b = v4[lane + 32 * i];
        kacc4(a, b, s, c, e);
    }
    double d = (double)s + (double)c + (double)e;
#pragma unroll
    for (int o = 16; o > 0; o >>= 1)
        d += __shfl_down_sync(0xffffffffu, d, o);
    return (float)d;
}

// One RNN phase (layer L of step t). Critical path: ih dot on preloaded registers.
// Shadow (after arrive): hh dot of layer (L+3)%4 for NEXT step, from cp.async-staged smem.
// Tail: preload next phase's ih row (volatile LDG) + cp.async next hh row (w_hh[L]).
template<int L>
__device__ __forceinline__ void rnn_phase(
    int t, int j, int lane, int tid, unsigned& ph,
    const float* __restrict__ w_ih, const float* __restrict__ w_hh,
    const float* __restrict__ b_ih, const float* __restrict__ b_hh,
    float* __restrict__ out,
    float* s_a, float* s_n, const float* s_hh_row, unsigned hh_smem_addr,
    ull polL, ull polF,
    Row8& W, double& hh_cons, double& hh_prod)
{
    gbar_wait(ph * GRID);                      // inputs published; W preloaded pre-wait
    const float* va = (L == 0) ? g_inp : g_hraw[L - 1];
    reinterpret_cast<float4*>(s_a)[tid] = reinterpret_cast<const float4*>(va)[tid];
    if (L > 0)
        reinterpret_cast<float4*>(s_n)[tid] =
            reinterpret_cast<const float4*>(g_hidn[L - 1])[tid];
    __syncthreads();
    const float4* a4 = reinterpret_cast<const float4*>(s_a);
    const float4* n4 = reinterpret_cast<const float4*>((L == 0) ? s_a : s_n);

    if (j < C) {
        double da = row_dot(W, a4, lane);      // zero load stall: weights in registers
#pragma unroll
        for (int o = 16; o > 0; o >>= 1)
            da += __shfl_down_sync(0xffffffffu, da, o);
        if (lane == 0) {
            // ref rounding: ((dih + b_ih) + dhh) + b_hh, all fp32 RN
            float pre = __fadd_rn(__fadd_rn(__fadd_rn((float)da, b_ih[L * C + j]),
                                            (float)hh_cons), b_hh[L * C + j]);
            float h  = fmaxf(pre, 0.f);
            float n  = __fsqrt_rn(__fmul_rn(h, h));
            float hn = __fdiv_rn(h, __fadd_rn(n, 1e-12f));
            if (L < 3) { g_hraw[L][j] = h; g_hidn[L][j] = hn; }
            else       { g_inp[j] = hn; out[(size_t)t * C + j] = hn; }
        }
    }
    gbar_arrive();                             // release ASAP; rest is barrier shadow

    if (j < C) {
        asm volatile("cp.async.wait_group 0;" ::: "memory");
        __syncwarp();
        // deferred: hh_{(L+3)%4}(next step) = w_hh[(L+3)%4] . norm(h_{L-1}(now))
        double db = smem_dot(reinterpret_cast<const float4*>(s_hh_row), n4, lane);
#pragma unroll
        for (int o = 16; o > 0; o >>= 1)
            db += __shfl_down_sync(0xffffffffu, db, o);
        hh_prod = db;                          // valid at lane 0 (only lane 0 consumes)
        // tail prefetch for next phase NL = (L+1)%4
        constexpr int NL = (L + 1) & 3;
        preload_row(W, reinterpret_cast<const F8*>(
                        w_ih + ((size_t)NL * C + j) * C), lane);
        stage_hh(hh_smem_addr, w_hh + ((size_t)L * C + j) * C, lane,
                 (L < 2) ? polL : polF);       // next phase's deferred layer is L
    }
    ++ph;
}

__global__ void __launch_bounds__(NT, 1) rnn_main(
    const float* __restrict__ x,
    const float* __restrict__ lp_w,  const float* __restrict__ lp_b,
    const float* __restrict__ lp_wout, const float* __restrict__ lp_bout,
    const float* __restrict__ w_ih,  const float* __restrict__ b_ih,
    const float* __restrict__ w_hh,  const float* __restrict__ b_hh,
    float* __restrict__ out, int T, int has_l)
{
    extern __shared__ float dsm[];
    float* s_a  = dsm;                 // 2048
    float* s_n  = dsm + C;             // 2048
    float* s_hh = dsm + 2 * C;         // 14 rows x 2048

    const int tid  = threadIdx.x;
    const int w    = tid >> 5;
    const int lane = tid & 31;
    const int bid  = blockIdx.x;
    const int j    = w * GRID + bid;   // warps 0..13 productive (j<2048)
    unsigned ph = 0;

    ull polL, polF;
    asm("createpolicy.fractional.L2::evict_last.b64 %0, 1.0;"  : "=l"(polL));
    asm("createpolicy.fractional.L2::evict_first.b64 %0, 1.0;" : "=l"(polF));

    unsigned smem_base = (unsigned)__cvta_generic_to_shared(dsm);
    const unsigned hh_smem_addr = smem_base + (unsigned)(2 * C + w * C) * 4u;
    const float* s_hh_row = s_hh + w * C;

    // ---------------- LengthProducer: 3 hidden Linear + LeakyReLU(0.2) ----------------
    for (int i = 0; i < 3; i++) {
        const float* vin = (i == 0) ? x : g_lp[(i - 1) & 1];
        reinterpret_cast<float4*>(s_a)[tid] = reinterpret_cast<const float4*>(vin)[tid];
        __syncthreads();
        if (j < C) {
            float d = dotLP(lp_w + (size_t)i * C * C + (size_t)j * C, s_a, lane);
            if (lane == 0) {
                float z = __fadd_rn(d, lp_b[i * C + j]);
                g_lp[i & 1][j] = (z >= 0.f) ? z : __fmul_rn(0.2f, z);
            }
        }
        gbar_arrive(); ++ph; gbar_wait(ph * GRID);
    }
    // ---------------- LP output scalar: l = min(|y@wout + bout|, 0.9999) ----------------
    if (bid == 0 && w == 0) {
        float d = dotLP(lp_wout, g_lp[0], lane);
        if (lane == 0 && has_l > 0) {
            float z = __fadd_rn(d, lp_bout[0]);
            out[(size_t)T * C] = fminf(fabsf(z), 0.9999f);
        }
    }

    // ---------------- RNN prologue ----------------
    // hh0(step 0) = w_hh[0] . x  (hid0[0] = x, raw). hh1=hh2=0 (hid0[1..3]=0);
    // hh3 recomputed in phase 0's shadow before its consumption at phase 3.
    double hh0 = 0.0, hh1 = 0.0, hh2 = 0.0, hh3 = 0.0;
    reinterpret_cast<float4*>(s_a)[tid] = reinterpret_cast<const float4*>(x)[tid];
    __syncthreads();
    Row8 W;
    if (j < C) {
        preload_row(W, reinterpret_cast<const F8*>(w_hh + (size_t)j * C), lane);
        double d0 = row_dot(W, reinterpret_cast<const float4*>(s_a), lane);
#pragma unroll
        for (int o = 16; o > 0; o >>= 1)
            d0 += __shfl_down_sync(0xffffffffu, d0, o);
        hh0 = d0;
        // prefetch phase (t=0, L=0): ih row + hh row of layer 3 (deferred at phase 0)
        preload_row(W, reinterpret_cast<const F8*>(w_ih + (size_t)j * C), lane);
        stage_hh(hh_smem_addr, w_hh + ((size_t)3 * C + j) * C, lane, polF);
    }
    gbar_arrive();
    ++ph;

    // ---------------- 4-layer ReLU RNN scan, T steps ----------------
    // Critical path per phase: ONE dot (ih) on register-preloaded weights.
    // hh dots run in the barrier shadow, results carried in hh0..hh3.
    for (int t = 0; t < T; t++) {
        rnn_phase<0>(t, j, lane, tid, ph, w_ih, w_hh, b_ih, b_hh, out,
                     s_a, s_n, s_hh_row, hh_smem_addr, polL, polF, W, hh0, hh3);
        rnn_phase<1>(t, j, lane, tid, ph, w_ih, w_hh, b_ih, b_hh, out,
                     s_a, s_n, s_hh_row, hh_smem_addr, polL, polF, W, hh1, hh0);
        rnn_phase<2>(t, j, lane, tid, ph, w_ih, w_hh, b_ih, b_hh, out,
                     s_a, s_n, s_hh_row, hh_smem_addr, polL, polF, W, hh2, hh1);
        rnn_phase<3>(t, j, lane, tid, ph, w_ih, w_hh, b_ih, b_hh, out,
                     s_a, s_n, s_hh_row, hh_smem_addr, polL, polF, W, hh3, hh2);
    }
    asm volatile("cp.async.wait_group 0;" ::: "memory");
}

extern "C" void kernel_launch(void* const* d_in, const int* in_sizes, int n_in,
                              void* d_out, int out_size) {
    const float* x       = (const float*)d_in[0];
    const float* lp_w    = (const float*)d_in[1];
    const float* lp_b    = (const float*)d_in[2];
    const float* lp_wout = (const float*)d_in[3];
    const float* lp_bout = (const float*)d_in[4];
    const float* w_ih    = (const float*)d_in[5];
    const float* b_ih    = (const float*)d_in[6];
    const float* w_hh    = (const float*)d_in[7];
    const float* b_hh    = (const float*)d_in[8];
    float* out = (float*)d_out;

    int T     = out_size / C;        // 512 seq rows
    int has_l = out_size - T * C;    // trailing scalar l present?

    cudaFuncSetAttribute(rnn_main, cudaFuncAttributeMaxDynamicSharedMemorySize, SMEM_BYTES);

    rnn_init<<<8, 256>>>(x);
    rnn_main<<<GRID, NT, SMEM_BYTES>>>(x, lp_w, lp_b, lp_wout, lp_bout,
                                       w_ih, b_ih, w_hh, b_hh, out, T, has_l);
}